// round 15
// baseline (speedup 1.0000x reference)
#include <cuda_runtime.h>
#include <math.h>

// Problem constants (fixed shapes)
#define B_  2
#define S_  1024
#define D_  1024
#define H_  16
#define DH_ 64
#define NB_ 256
#define NC_ 257     // compressed keys = mem + 256 blocks
#define FD_ 4096
#define ROWS_ (B_*S_)   // 2048
#define FULLMASK 0xffffffffu

// ---------------- scratch (static device arrays; no allocation) ----------------
__device__ float g_xr[B_*S_*D_];
__device__ float g_h [B_*S_*D_];
__device__ float g_q [B_*S_*D_];
__device__ float g_k [B_*S_*D_];
__device__ float g_v [B_*S_*D_];
__device__ float g_qr[B_*S_*D_];
__device__ float g_kr[B_*S_*D_];
__device__ float g_kc[B_*NC_*H_*DH_];
__device__ float g_vc[B_*NC_*H_*DH_];
__device__ float g_gate[B_*S_*48];
__device__ float g_o [B_*S_*D_];
__device__ float g_x1[B_*S_*D_];
__device__ float g_m [B_*S_*D_];
__device__ float g_act[B_*S_*FD_];
__device__ float g_ctab[S_*32];
__device__ float g_stab[S_*32];

// ---------------- K1: xr = l0*x + l1*x0 ; h = rmsnorm(xr) ----------------
__global__ void k_rms1(const float* __restrict__ x, const float* __restrict__ x0,
                       const float* __restrict__ lam) {
    const int row = blockIdx.x;
    const int t = threadIdx.x;
    const float l0 = lam[0], l1 = lam[1];
    const size_t base = (size_t)row * D_;
    __shared__ float red[8];
    __shared__ float s_inv;
    float ss = 0.f;
    for (int i = t; i < D_; i += 256) {
        float v = l0 * x[base + i] + l1 * x0[base + i];
        g_xr[base + i] = v;
        ss += v * v;
    }
#pragma unroll
    for (int o = 16; o; o >>= 1) ss += __shfl_xor_sync(FULLMASK, ss, o);
    if ((t & 31) == 0) red[t >> 5] = ss;
    __syncthreads();
    if (t == 0) {
        float tot = 0.f;
        for (int w = 0; w < 8; w++) tot += red[w];
        s_inv = rsqrtf(tot / (float)D_ + 1e-6f);
    }
    __syncthreads();
    const float inv = s_inv;
    for (int i = t; i < D_; i += 256) g_h[base + i] = g_xr[base + i] * inv;
}

__global__ void k_rms2() {
    const int row = blockIdx.x;
    const int t = threadIdx.x;
    const size_t base = (size_t)row * D_;
    __shared__ float red[8];
    __shared__ float s_inv;
    float ss = 0.f;
    for (int i = t; i < D_; i += 256) { float v = g_x1[base + i]; ss += v * v; }
#pragma unroll
    for (int o = 16; o; o >>= 1) ss += __shfl_xor_sync(FULLMASK, ss, o);
    if ((t & 31) == 0) red[t >> 5] = ss;
    __syncthreads();
    if (t == 0) {
        float tot = 0.f;
        for (int w = 0; w < 8; w++) tot += red[w];
        s_inv = rsqrtf(tot / (float)D_ + 1e-6f);
    }
    __syncthreads();
    const float inv = s_inv;
    for (int i = t; i < D_; i += 256) g_m[base + i] = g_x1[base + i] * inv;
}

// ================= 3xTF32 tensor-core GEMM (error-compensated, mma.sync m16n8k8) =================
// CTA tile 128x128, BK=32, 8 warps (2x4), warp tile 64x32, cp.async double buffer.
#define ASZ 4608    // 128*36
#define BSZ 4352    // 32*136
#define BUFSZ 8960  // ASZ+BSZ
#define SMEM_BYTES (2*BUFSZ*4)   // 71680

__device__ __forceinline__ void cp16(void* dst_smem, const void* src) {
    unsigned d = (unsigned)__cvta_generic_to_shared(dst_smem);
    asm volatile("cp.async.ca.shared.global [%0], [%1], 16;" :: "r"(d), "l"(src));
}

__device__ __forceinline__ unsigned tf32_rna(float x) {
    unsigned r;
    asm("cvt.rna.tf32.f32 %0, %1;" : "=r"(r) : "f"(x));
    return r;
}
__device__ __forceinline__ void split_tf32(float x, unsigned &hi, unsigned &lo) {
    hi = tf32_rna(x);
    lo = tf32_rna(x - __uint_as_float(hi));
}
__device__ __forceinline__ void mma_tf32(float c[4], const unsigned a[4], const unsigned b[2]) {
    asm volatile(
        "mma.sync.aligned.m16n8k8.row.col.f32.tf32.tf32.f32 "
        "{%0,%1,%2,%3}, {%4,%5,%6,%7}, {%8,%9}, {%0,%1,%2,%3};"
        : "+f"(c[0]), "+f"(c[1]), "+f"(c[2]), "+f"(c[3])
        : "r"(a[0]), "r"(a[1]), "r"(a[2]), "r"(a[3]), "r"(b[0]), "r"(b[1]));
}

// EPI: 0 = plain store, 1 = +Add, 2 = relu^2
template <int EPI>
__device__ __forceinline__ void mma_gemm(const float* __restrict__ A,
                                         const float* __restrict__ Bm,
                                         float* __restrict__ C,
                                         const float* __restrict__ Add,
                                         int N, int K) {
    extern __shared__ float smem[];
    const int tid = threadIdx.x;
    const int warp = tid >> 5, lane = tid & 31;
    const int wm = warp >> 2, wn = warp & 3;
    const int g = lane >> 2, tg = lane & 3;
    const int tileM = blockIdx.y * 128, tileN = blockIdx.x * 128;

    float acc[4][4][4];
#pragma unroll
    for (int mt = 0; mt < 4; mt++)
#pragma unroll
        for (int nt = 0; nt < 4; nt++)
#pragma unroll
            for (int c = 0; c < 4; c++) acc[mt][nt][c] = 0.f;

    const int ar = tid >> 3, ac0 = (tid & 7) << 2;
    const int bk = tid >> 5, bn0 = (tid & 31) << 2;
    const int niter = K >> 5;

    {
        float* Ab = smem;
        float* Bb = smem + ASZ;
#pragma unroll
        for (int p = 0; p < 4; p++) {
            int r = ar + p * 32;
            cp16(Ab + r * 36 + ac0, A + (size_t)(tileM + r) * K + ac0);
        }
#pragma unroll
        for (int p = 0; p < 4; p++) {
            int kk = bk + p * 8;
            cp16(Bb + kk * 136 + bn0, Bm + (size_t)kk * N + tileN + bn0);
        }
        asm volatile("cp.async.commit_group;" ::: "memory");
    }

    for (int i = 0; i < niter; i++) {
        if (i + 1 < niter) {
            const int k0 = (i + 1) << 5;
            float* Ab = smem + ((i + 1) & 1) * BUFSZ;
            float* Bb = Ab + ASZ;
#pragma unroll
            for (int p = 0; p < 4; p++) {
                int r = ar + p * 32;
                cp16(Ab + r * 36 + ac0, A + (size_t)(tileM + r) * K + k0 + ac0);
            }
#pragma unroll
            for (int p = 0; p < 4; p++) {
                int kk = bk + p * 8;
                cp16(Bb + kk * 136 + bn0, Bm + (size_t)(k0 + kk) * N + tileN + bn0);
            }
            asm volatile("cp.async.commit_group;" ::: "memory");
            asm volatile("cp.async.wait_group 1;" ::: "memory");
        } else {
            asm volatile("cp.async.wait_group 0;" ::: "memory");
        }
        __syncthreads();

        const float* Ab = smem + (i & 1) * BUFSZ;
        const float* Bb = Ab + ASZ;
#pragma unroll
        for (int kt = 0; kt < 4; kt++) {
            unsigned afh[4][4], afl[4][4], bfh[4][2], bfl[4][2];
#pragma unroll
            for (int mt = 0; mt < 4; mt++) {
                const float* ap = Ab + (wm * 64 + mt * 16 + g) * 36 + kt * 8 + tg;
                split_tf32(ap[0],          afh[mt][0], afl[mt][0]);
                split_tf32(ap[8 * 36],     afh[mt][1], afl[mt][1]);
                split_tf32(ap[4],          afh[mt][2], afl[mt][2]);
                split_tf32(ap[8 * 36 + 4], afh[mt][3], afl[mt][3]);
            }
#pragma unroll
            for (int nt = 0; nt < 4; nt++) {
                const float* bp = Bb + (kt * 8 + tg) * 136 + wn * 32 + nt * 8 + g;
                split_tf32(bp[0],       bfh[nt][0], bfl[nt][0]);
                split_tf32(bp[4 * 136], bfh[nt][1], bfl[nt][1]);
            }
#pragma unroll
            for (int mt = 0; mt < 4; mt++)
#pragma unroll
                for (int nt = 0; nt < 4; nt++) {
                    mma_tf32(acc[mt][nt], afh[mt], bfl[nt]);
                    mma_tf32(acc[mt][nt], afl[mt], bfh[nt]);
                    mma_tf32(acc[mt][nt], afh[mt], bfh[nt]);
                }
        }
        __syncthreads();
    }

#pragma unroll
    for (int mt = 0; mt < 4; mt++) {
#pragma unroll
        for (int nt = 0; nt < 4; nt++) {
            const int row = tileM + wm * 64 + mt * 16 + g;
            const int col = tileN + wn * 32 + nt * 8 + tg * 2;
            float2 v0 = make_float2(acc[mt][nt][0], acc[mt][nt][1]);
            float2 v1 = make_float2(acc[mt][nt][2], acc[mt][nt][3]);
            size_t i0 = (size_t)row * N + col;
            size_t i1 = (size_t)(row + 8) * N + col;
            if (EPI == 1) {
                float2 a0 = *(const float2*)(Add + i0);
                float2 a1 = *(const float2*)(Add + i1);
                v0.x += a0.x; v0.y += a0.y;
                v1.x += a1.x; v1.y += a1.y;
            } else if (EPI == 2) {
                v0.x = fmaxf(v0.x, 0.f); v0.x *= v0.x;
                v0.y = fmaxf(v0.y, 0.f); v0.y *= v0.y;
                v1.x = fmaxf(v1.x, 0.f); v1.x *= v1.x;
                v1.y = fmaxf(v1.y, 0.f); v1.y *= v1.y;
            }
            *(float2*)(C + i0) = v0;
            *(float2*)(C + i1) = v1;
        }
    }
}

__global__ void __launch_bounds__(256) gemm_qkv_t(const float* __restrict__ Wq,
                                                  const float* __restrict__ Wk,
                                                  const float* __restrict__ Wv) {
    const int z = blockIdx.z;
    const float* W = (z == 0) ? Wq : (z == 1) ? Wk : Wv;
    float* Cp = (z == 0) ? g_q : (z == 1) ? g_k : g_v;
    mma_gemm<0>(g_h, W, Cp, nullptr, D_, D_);
}
__global__ void __launch_bounds__(256) gemm_o_t(const float* __restrict__ W) {
    mma_gemm<1>(g_o, W, g_x1, g_xr, D_, D_);
}
__global__ void __launch_bounds__(256) gemm_fc_t(const float* __restrict__ W) {
    mma_gemm<2>(g_m, W, g_act, nullptr, FD_, D_);
}
__global__ void __launch_bounds__(256) gemm_proj_t(const float* __restrict__ W, float* __restrict__ out) {
    mma_gemm<1>(g_act, W, out, g_x1, D_, FD_);
}

// ---------------- gates: tiled, 16 rows x 48 cols, conflict-free (pitch 129) ----------------
__global__ void __launch_bounds__(768) k_gate3(const float* __restrict__ Wg) {
    __shared__ float sh[16 * 129];
    __shared__ float sw[128 * 48];
    const int t = threadIdx.x;
    const int r = t / 48, c = t % 48;
    const int row0 = blockIdx.x * 16;
    float acc = 0.f;
    for (int k0 = 0; k0 < D_; k0 += 128) {
        for (int i = t; i < 16 * 128; i += 768)
            sh[(i >> 7) * 129 + (i & 127)] = g_h[(size_t)(row0 + (i >> 7)) * D_ + k0 + (i & 127)];
        for (int i = t; i < 128 * 48; i += 768)
            sw[i] = Wg[(size_t)(k0 + i / 48) * 48 + (i % 48)];
        __syncthreads();
        const float* hr = &sh[r * 129];
#pragma unroll 8
        for (int kk = 0; kk < 128; kk++) acc += hr[kk] * sw[kk * 48 + c];
        __syncthreads();
    }
    g_gate[(size_t)(row0 + r) * 48 + c] = 1.f / (1.f + expf(-acc));
}

// ---------------- block compression v2: one block per (b,n), all 16 heads ----------------
// W working set (Wck+Wcv = 128KB) becomes L1-resident per block (re-read across the
// 4 h-iterations), cutting L2 W traffic 16x vs the per-(b,n,h) version.
// Inner sum is ascending-r: numerically identical to the previous kernel.
__global__ void __launch_bounds__(256) k_compress2(const float* __restrict__ pos_k,
                                                   const float* __restrict__ pos_v,
                                                   const float* __restrict__ Wck,
                                                   const float* __restrict__ Wcv) {
    const int idx = blockIdx.x;          // B*NB = 512
    const int n = idx & (NB_ - 1);
    const int b = idx >> 8;
    const int t = threadIdx.x;           // 256
    const int d = t & 63, hq = t >> 6;   // hq 0..3

    __shared__ float kb[16][256];
    __shared__ float vb[16][256];

    for (int e = t; e < 16 * 256; e += 256) {
        const int h = e >> 8, r = e & 255;
        const int sp = r >> 6, dd = r & 63;
        const size_t src = ((size_t)(b * S_ + n * 4 + sp) * H_ + h) * DH_ + dd;
        kb[h][r] = g_k[src] + pos_k[(h * 4 + sp) * DH_ + dd];
        vb[h][r] = g_v[src] + pos_v[(h * 4 + sp) * DH_ + dd];
    }
    __syncthreads();

#pragma unroll
    for (int hh = 0; hh < 4; hh++) {
        const int h = hq * 4 + hh;
        float ak = 0.f, av = 0.f;
        const float* kbh = kb[h];
        const float* vbh = vb[h];
#pragma unroll 8
        for (int r = 0; r < 256; r++) {
            ak += kbh[r] * Wck[r * DH_ + d];
            av += vbh[r] * Wcv[r * DH_ + d];
        }
        const size_t dst = ((size_t)(b * NC_ + (n + 1)) * H_ + h) * DH_ + d;
        g_kc[dst] = ak;
        g_vc[dst] = av;
    }
}

__global__ void k_memfill(const float* __restrict__ mem_k, const float* __restrict__ mem_v) {
    const int i = blockIdx.x * blockDim.x + threadIdx.x;  // B*H*DH = 2048
    if (i >= B_ * H_ * DH_) return;
    const int d = i & 63, h = (i >> 6) & (H_ - 1), b = i >> 10;
    const size_t dst = ((size_t)(b * NC_ + 0) * H_ + h) * DH_ + d;
    g_kc[dst] = mem_k[h * DH_ + d];
    g_vc[dst] = mem_v[h * DH_ + d];
}

// ---------------- trig table + RoPE ----------------
__global__ void k_trig() {
    const int i = blockIdx.x * blockDim.x + threadIdx.x;  // S*32
    if (i >= S_ * 32) return;
    const int p = i & 31;
    const int s = i >> 5;
    const float inv = exp2f(-(float)p * (13.287712379549449f / 32.f));
    const float tt = (float)s * inv;
    g_ctab[i] = cosf(tt);
    g_stab[i] = sinf(tt);
}

__global__ void k_rope() {
    const int i = blockIdx.x * blockDim.x + threadIdx.x;  // B*S*H*32
    if (i >= B_ * S_ * H_ * 32) return;
    const int p = i & 31;
    const int h = (i >> 5) & (H_ - 1);
    const int s = (i >> 9) & (S_ - 1);
    const int b = i >> 19;
    const float c  = g_ctab[s * 32 + p];
    const float sn = g_stab[s * 32 + p];
    const size_t base = ((size_t)(b * S_ + s) * H_ + h) * DH_;
    float q1 = g_q[base + p], q2 = g_q[base + 32 + p];
    g_qr[base + p]      = q1 * c - q2 * sn;
    g_qr[base + 32 + p] = q1 * sn + q2 * c;
    float k1 = g_k[base + p], k2 = g_k[base + 32 + p];
    g_kr[base + p]      = k1 * c - k2 * sn;
    g_kr[base + 32 + p] = k1 * sn + k2 * c;
}

// ---------------- attention v3: smem-tiled compressed + sliding, warp-per-query ----------------
#define KTP 65     // tile row pitch (floats)

__global__ void __launch_bounds__(256) k_attn3() {
    const int blk = blockIdx.x;            // B*H*(S/8) = 4096
    const int s0 = (blk & 127) << 3;
    const int h = (blk >> 7) & (H_ - 1);
    const int b = blk >> 11;
    const int w = threadIdx.x >> 5;        // warp = query within tile
    const int l = threadIdx.x & 31;
    const int s = s0 + w;
    const int tid = threadIdx.x;

    __shared__ float qs[8][64];
    __shared__ float qrs[8][64];
    __shared__ float sc[8][260];
    __shared__ float buf[5200];

    const size_t qbase = ((size_t)(b * S_ + s) * H_ + h) * DH_;
    qs [w][l]      = g_q [qbase + l];
    qs [w][l + 32] = g_q [qbase + 32 + l];
    qrs[w][l]      = g_qr[qbase + l];
    qrs[w][l + 32] = g_qr[qbase + 32 + l];
    __syncwarp();

    const int nvisB = (s >= 3) ? (((s - 3) >> 2) + 1) : 0;
    const int nk = nvisB + 1;
    const int nkb = (((s0 + 7) >= 3) ? (((s0 + 4) >> 2) + 1) : 0) + 1;

    const float* kcbase = g_kc + ((size_t)b * NC_ * H_ + h) * DH_;
    const float* vcbase = g_vc + ((size_t)b * NC_ * H_ + h) * DH_;
    const float* qsw  = qs[w];
    const float* qrsw = qrs[w];

    // ===== Phase A: compressed scores (tiled kc) =====
    float mymax = -1e30f;
    for (int n0 = 0; n0 < nkb; n0 += 64) {
        __syncthreads();
#pragma unroll
        for (int i = 0; i < 16; i++) {
            const int e = tid + 256 * i;
            const int r = e >> 6, c = e & 63;
            int n = n0 + r; if (n > NC_ - 1) n = NC_ - 1;
            buf[r * KTP + c] = kcbase[(size_t)n * (H_ * DH_) + c];
        }
        __syncthreads();
#pragma unroll
        for (int sub = 0; sub < 2; sub++) {
            const int n = n0 + sub * 32 + l;
            if (n < nk) {
                const float* kr_ = &buf[(sub * 32 + l) * KTP];
                float a = 0.f;
#pragma unroll
                for (int d = 0; d < 64; d++) a += qsw[d] * kr_[d];
                a *= 0.125f;
                sc[w][n] = a;
                mymax = fmaxf(mymax, a);
            }
        }
    }
#pragma unroll
    for (int o = 16; o; o >>= 1) mymax = fmaxf(mymax, __shfl_xor_sync(FULLMASK, mymax, o));

    float mysum = 0.f;
    for (int n = l; n < nk; n += 32) {
        float e = expf(sc[w][n] - mymax);
        sc[w][n] = e;
        mysum += e;
    }
#pragma unroll
    for (int o = 16; o; o >>= 1) mysum += __shfl_xor_sync(FULLMASK, mysum, o);
    const float rcs = 1.f / mysum;

    // ===== top-4 blocks =====
    float tv[4] = {-1.f, -1.f, -1.f, -1.f};
    int   ti[4] = {0, 0, 0, 0};
    for (int n = l; n < nk; n += 32) {
        if (n >= 1) {
            float vI = sc[w][n];
            if (vI > tv[3]) {
                int p2 = 3;
                while (p2 > 0 && vI > tv[p2 - 1]) {
                    tv[p2] = tv[p2 - 1]; ti[p2] = ti[p2 - 1]; p2--;
                }
                tv[p2] = vI; ti[p2] = n - 1;
            }
        }
    }
#pragma unroll
    for (int off = 16; off; off >>= 1) {
        float ov[4]; int oi[4];
#pragma unroll
        for (int m = 0; m < 4; m++) {
            ov[m] = __shfl_xor_sync(FULLMASK, tv[m], off);
            oi[m] = __shfl_xor_sync(FULLMASK, ti[m], off);
        }
#pragma unroll
        for (int m = 0; m < 4; m++) {
            float v2 = ov[m]; int i2 = oi[m];
            if ((v2 > tv[3]) || (v2 == tv[3] && i2 < ti[3])) {
                int p2 = 3;
                while (p2 > 0 && ((v2 > tv[p2 - 1]) || (v2 == tv[p2 - 1] && i2 < ti[p2 - 1]))) {
                    tv[p2] = tv[p2 - 1]; ti[p2] = ti[p2 - 1]; p2--;
                }
                tv[p2] = v2; ti[p2] = i2;
            }
        }
    }

    // ===== Phase B: compressed PV =====
    float oc0 = 0.f, oc1 = 0.f;
    for (int n0 = 0; n0 < nkb; n0 += 64) {
        __syncthreads();
#pragma unroll
        for (int i = 0; i < 16; i++) {
            const int e = tid + 256 * i;
            const int r = e >> 6, c = e & 63;
            int n = n0 + r; if (n > NC_ - 1) n = NC_ - 1;
            buf[r * KTP + c] = vcbase[(size_t)n * (H_ * DH_) + c];
        }
        __syncthreads();
        const int jmax = (nk - n0 < 64) ? (nk - n0) : 64;
        for (int j = 0; j < jmax; j++) {
            const float pn = sc[w][n0 + j];
            oc0 += pn * buf[j * KTP + l];
            oc1 += pn * buf[j * KTP + l + 32];
        }
    }
    oc0 *= rcs; oc1 *= rcs;

    // ===== Phase C: fine (20 gathered keys) =====
    float fe = 0.f;
    int fkp = 0;
    {
        float fs = -1e30f;
        if (l < 20) {
            const int m = l >> 2, sp = l & 3;
            const int blk2 = (m == 4) ? (s >> 2) : ti[m];
            fkp = blk2 * 4 + sp;
            const bool vis = ((m == 4) || (tv[m] > 0.f)) && (fkp <= s);
            if (vis) {
                const float* kp = g_kr + ((size_t)(b * S_ + fkp) * H_ + h) * DH_;
                fs = 0.f;
#pragma unroll
                for (int d = 0; d < 64; d += 4) {
                    float4 x = *(const float4*)(qrsw + d);
                    float4 y = *(const float4*)(kp + d);
                    fs += x.x * y.x + x.y * y.y + x.z * y.z + x.w * y.w;
                }
                fs *= 0.125f;
            }
        }
        float fmx = fs;
#pragma unroll
        for (int o = 16; o; o >>= 1) fmx = fmaxf(fmx, __shfl_xor_sync(FULLMASK, fmx, o));
        fe = (fs > -1e29f) ? expf(fs - fmx) : 0.f;
    }
    float fsum = fe;
#pragma unroll
    for (int o = 16; o; o >>= 1) fsum += __shfl_xor_sync(FULLMASK, fsum, o);
    const float rcf = 1.f / fsum;

    float of0 = 0.f, of1 = 0.f;
    for (int j = 0; j < 20; j++) {
        float pj = __shfl_sync(FULLMASK, fe, j);
        int kj   = __shfl_sync(FULLMASK, fkp, j);
        const float* p = g_v + ((size_t)(b * S_ + kj) * H_ + h) * DH_;
        of0 += pj * p[l];
        of1 += pj * p[l + 32];
    }
    of0 *= rcf; of1 *= rcf;

    // ===== Phase D: sliding window =====
    __syncthreads();
    {
        const int base = s0 - 31;
#pragma unroll
        for (int i = 0; i < 10; i++) {
            const int e = tid + 256 * i;
            const int r = e >> 6, c = e & 63;
            int rs = base + r; if (rs < 0) rs = 0;
            const size_t src = ((size_t)(b * S_ + rs) * H_ + h) * DH_ + c;
            buf[r * KTP + c]        = g_kr[src];
            buf[2600 + r * KTP + c] = g_v [src];
        }
    }
    __syncthreads();

    float se = 0.f;
    {
        const int pos = s - l;
        float ssv = -1e30f;
        if (pos >= 0) {
            const float* kr_ = &buf[(w + 31 - l) * KTP];
            ssv = 0.f;
#pragma unroll
            for (int d = 0; d < 64; d++) ssv += qrsw[d] * kr_[d];
            ssv *= 0.125f;
        }
        float smx = ssv;
#pragma unroll
        for (int o = 16; o; o >>= 1) smx = fmaxf(smx, __shfl_xor_sync(FULLMASK, smx, o));
        se = (ssv > -1e29f) ? expf(ssv - smx) : 0.f;
    }
    float ssum = se;
#pragma unroll
    for (int o = 16; o; o >>= 1) ssum += __shfl_xor_sync(FULLMASK, ssum, o);
    const float rcw = 1.f / ssum;

    float os0 = 0.f, os1 = 0.f;
    {
        const int wmax = s < 31 ? s : 31;
        for (int w2 = 0; w2 <= wmax; w2++) {
            float pj = __shfl_sync(FULLMASK, se, w2);
            const float* vr = &buf[2600 + (w + 31 - w2) * KTP];
            os0 += pj * vr[l];
            os1 += pj * vr[l + 32];
        }
    }
    os0 *= rcw; os1 *= rcw;

    // ===== gate + write =====
    const float* gg = g_gate + (size_t)(b * S_ + s) * 48 + h * 3;
    const float g0 = gg[0], g1 = gg[1], g2 = gg[2];
    float* op = g_o + (size_t)(b * S_ + s) * D_ + h * DH_;
    op[l]      = g0 * oc0 + g1 * of0 + g2 * os0;
    op[l + 32] = g0 * oc1 + g1 * of1 + g2 * os1;
}

// ---------------- launch ----------------
extern "C" void kernel_launch(void* const* d_in, const int* in_sizes, int n_in,
                              void* d_out, int out_size) {
    (void)in_sizes; (void)n_in; (void)out_size;
    const float* x     = (const float*)d_in[0];
    const float* x0    = (const float*)d_in[2];
    const float* lam   = (const float*)d_in[3];
    const float* Wq    = (const float*)d_in[4];
    const float* Wk    = (const float*)d_in[5];
    const float* Wv    = (const float*)d_in[6];
    const float* pos_k = (const float*)d_in[7];
    const float* pos_v = (const float*)d_in[8];
    const float* Wck   = (const float*)d_in[9];
    const float* Wcv   = (const float*)d_in[10];
    const float* mem_k = (const float*)d_in[11];
    const float* mem_v = (const float*)d_in[12];
    const float* Wg    = (const float*)d_in[13];
    const float* Wo    = (const float*)d_in[14];
    const float* Wfc   = (const float*)d_in[15];
    const float* Wproj = (const float*)d_in[16];
    float* out = (float*)d_out;

    cudaFuncSetAttribute(gemm_qkv_t,  cudaFuncAttributeMaxDynamicSharedMemorySize, SMEM_BYTES);
    cudaFuncSetAttribute(gemm_o_t,    cudaFuncAttributeMaxDynamicSharedMemorySize, SMEM_BYTES);
    cudaFuncSetAttribute(gemm_fc_t,   cudaFuncAttributeMaxDynamicSharedMemorySize, SMEM_BYTES);
    cudaFuncSetAttribute(gemm_proj_t, cudaFuncAttributeMaxDynamicSharedMemorySize, SMEM_BYTES);

    k_trig<<<(S_ * 32) / 256, 256>>>();
    k_rms1<<<ROWS_, 256>>>(x, x0, lam);

    dim3 gqkv(D_ / 128, ROWS_ / 128, 3);   // (8,16,3)
    gemm_qkv_t<<<gqkv, 256, SMEM_BYTES>>>(Wq, Wk, Wv);
    k_gate3<<<ROWS_ / 16, 768>>>(Wg);

    k_compress2<<<B_ * NB_, 256>>>(pos_k, pos_v, Wck, Wcv);
    k_memfill<<<(B_ * H_ * DH_ + 255) / 256, 256>>>(mem_k, mem_v);
    k_rope<<<(B_ * S_ * H_ * 32) / 256, 256>>>();

    k_attn3<<<B_ * H_ * (S_ / 8), 256>>>();

    dim3 g1(D_ / 128, ROWS_ / 128);        // (8,16)
    gemm_o_t<<<g1, 256, SMEM_BYTES>>>(Wo);         // x1 = xr + o@Wo
    k_rms2<<<ROWS_, 256>>>();                      // m = rmsnorm(x1)

    dim3 g2(FD_ / 128, ROWS_ / 128);       // (32,16)
    gemm_fc_t<<<g2, 256, SMEM_BYTES>>>(Wfc);       // act = relu(m@Wfc)^2
    gemm_proj_t<<<g1, 256, SMEM_BYTES>>>(Wproj, out);  // out = x1 + act@Wproj
}

// round 16
// speedup vs baseline: 1.0021x; 1.0021x over previous
#include <cuda_runtime.h>
#include <math.h>

// Problem constants (fixed shapes)
#define B_  2
#define S_  1024
#define D_  1024
#define H_  16
#define DH_ 64
#define NB_ 256
#define NC_ 257     // compressed keys = mem + 256 blocks
#define FD_ 4096
#define ROWS_ (B_*S_)   // 2048
#define FULLMASK 0xffffffffu

// ---------------- scratch (static device arrays; no allocation) ----------------
__device__ float g_xr[B_*S_*D_];
__device__ float g_h [B_*S_*D_];
__device__ float g_q [B_*S_*D_];
__device__ float g_k [B_*S_*D_];
__device__ float g_v [B_*S_*D_];
__device__ float g_qr[B_*S_*D_];
__device__ float g_kr[B_*S_*D_];
__device__ float g_kc[B_*NC_*H_*DH_];
__device__ float g_vc[B_*NC_*H_*DH_];
__device__ float g_gate[B_*S_*48];
__device__ float g_x1[B_*S_*D_];
__device__ float g_ctab[S_*32];
__device__ float g_stab[S_*32];

// pre-split GEMM operands (fp32 values already rounded to tf32 grid)
__device__ float g_h_hi [B_*S_*D_],  g_h_lo [B_*S_*D_];
__device__ float g_o_hi [B_*S_*D_],  g_o_lo [B_*S_*D_];
__device__ float g_m_hi [B_*S_*D_],  g_m_lo [B_*S_*D_];
__device__ float g_act_hi[B_*S_*FD_], g_act_lo[B_*S_*FD_];
__device__ float g_Wq_hi[D_*D_],  g_Wq_lo[D_*D_];
__device__ float g_Wk_hi[D_*D_],  g_Wk_lo[D_*D_];
__device__ float g_Wv_hi[D_*D_],  g_Wv_lo[D_*D_];
__device__ float g_Wo_hi[D_*D_],  g_Wo_lo[D_*D_];
__device__ float g_Wfc_hi[D_*FD_], g_Wfc_lo[D_*FD_];
__device__ float g_Wpr_hi[FD_*D_], g_Wpr_lo[FD_*D_];

// ---------------- helpers ----------------
__device__ __forceinline__ void cp16(void* dst_smem, const void* src) {
    unsigned d = (unsigned)__cvta_generic_to_shared(dst_smem);
    asm volatile("cp.async.ca.shared.global [%0], [%1], 16;" :: "r"(d), "l"(src));
}
__device__ __forceinline__ unsigned tf32_rna(float x) {
    unsigned r;
    asm("cvt.rna.tf32.f32 %0, %1;" : "=r"(r) : "f"(x));
    return r;
}
// split into fp32 values on the tf32 grid (bit-identical to in-loop split_tf32)
__device__ __forceinline__ void split_f(float x, float &hi, float &lo) {
    hi = __uint_as_float(tf32_rna(x));
    lo = __uint_as_float(tf32_rna(x - hi));
}
__device__ __forceinline__ void mma_tf32(float c[4], const unsigned a[4], const unsigned b[2]) {
    asm volatile(
        "mma.sync.aligned.m16n8k8.row.col.f32.tf32.tf32.f32 "
        "{%0,%1,%2,%3}, {%4,%5,%6,%7}, {%8,%9}, {%0,%1,%2,%3};"
        : "+f"(c[0]), "+f"(c[1]), "+f"(c[2]), "+f"(c[3])
        : "r"(a[0]), "r"(a[1]), "r"(a[2]), "r"(a[3]), "r"(b[0]), "r"(b[1]));
}

// ---------------- weight split: W -> Whi, Wlo (same layout) ----------------
__global__ void __launch_bounds__(256) k_wsplit(const float* __restrict__ W,
                                                float* __restrict__ Wh,
                                                float* __restrict__ Wl, int n) {
    const int i = blockIdx.x * 256 + threadIdx.x;
    if (i < n) {
        float hi, lo;
        split_f(W[i], hi, lo);
        Wh[i] = hi; Wl[i] = lo;
    }
}

// ---------------- K1: xr = l0*x + l1*x0 ; h = rmsnorm(xr) (+ split h) ----------------
__global__ void k_rms1(const float* __restrict__ x, const float* __restrict__ x0,
                       const float* __restrict__ lam) {
    const int row = blockIdx.x;
    const int t = threadIdx.x;
    const float l0 = lam[0], l1 = lam[1];
    const size_t base = (size_t)row * D_;
    __shared__ float red[8];
    __shared__ float s_inv;
    float ss = 0.f;
    for (int i = t; i < D_; i += 256) {
        float v = l0 * x[base + i] + l1 * x0[base + i];
        g_xr[base + i] = v;
        ss += v * v;
    }
#pragma unroll
    for (int o = 16; o; o >>= 1) ss += __shfl_xor_sync(FULLMASK, ss, o);
    if ((t & 31) == 0) red[t >> 5] = ss;
    __syncthreads();
    if (t == 0) {
        float tot = 0.f;
        for (int w = 0; w < 8; w++) tot += red[w];
        s_inv = rsqrtf(tot / (float)D_ + 1e-6f);
    }
    __syncthreads();
    const float inv = s_inv;
    for (int i = t; i < D_; i += 256) {
        float v = g_xr[base + i] * inv;
        g_h[base + i] = v;                 // fp32 (k_gate)
        float hi, lo; split_f(v, hi, lo);
        g_h_hi[base + i] = hi; g_h_lo[base + i] = lo;
    }
}

// rmsnorm(x1) -> m (split only; m feeds only gemm_fc)
__global__ void k_rms2() {
    const int row = blockIdx.x;
    const int t = threadIdx.x;
    const size_t base = (size_t)row * D_;
    __shared__ float red[8];
    __shared__ float s_inv;
    float ss = 0.f;
    for (int i = t; i < D_; i += 256) { float v = g_x1[base + i]; ss += v * v; }
#pragma unroll
    for (int o = 16; o; o >>= 1) ss += __shfl_xor_sync(FULLMASK, ss, o);
    if ((t & 31) == 0) red[t >> 5] = ss;
    __syncthreads();
    if (t == 0) {
        float tot = 0.f;
        for (int w = 0; w < 8; w++) tot += red[w];
        s_inv = rsqrtf(tot / (float)D_ + 1e-6f);
    }
    __syncthreads();
    const float inv = s_inv;
    for (int i = t; i < D_; i += 256) {
        float v = g_x1[base + i] * inv;
        float hi, lo; split_f(v, hi, lo);
        g_m_hi[base + i] = hi; g_m_lo[base + i] = lo;
    }
}

// ================= 3xTF32 GEMM with PRE-SPLIT operands =================
// CTA 128x128, BK=32, 8 warps (2x4). smem per buffer: Ahi|Alo|Bhi|Blo.
#define ASZ 4608    // 128*36
#define BSZ 4352    // 32*136
#define BUFP (2*ASZ + 2*BSZ)          // 17920 floats
#define SMEM_PRE_BYTES (2*BUFP*4)     // 143360

// EPI: 0 = plain store C, 1 = C = AB + Add, 2 = split-store relu(AB)^2 to Ch/Cl
template <int EPI>
__device__ __forceinline__ void mma_gemm_pre(const float* __restrict__ Ah,
                                             const float* __restrict__ Al,
                                             const float* __restrict__ Bh,
                                             const float* __restrict__ Bl,
                                             float* __restrict__ C,
                                             const float* __restrict__ Add,
                                             float* __restrict__ Ch,
                                             float* __restrict__ Cl,
                                             int N, int K) {
    extern __shared__ float smem[];
    const int tid = threadIdx.x;
    const int warp = tid >> 5, lane = tid & 31;
    const int wm = warp >> 2, wn = warp & 3;
    const int g = lane >> 2, tg = lane & 3;
    const int tileM = blockIdx.y * 128, tileN = blockIdx.x * 128;

    float acc[4][4][4];
#pragma unroll
    for (int mt = 0; mt < 4; mt++)
#pragma unroll
        for (int nt = 0; nt < 4; nt++)
#pragma unroll
            for (int c = 0; c < 4; c++) acc[mt][nt][c] = 0.f;

    const int ar = tid >> 3, ac0 = (tid & 7) << 2;
    const int bk = tid >> 5, bn0 = (tid & 31) << 2;
    const int niter = K >> 5;

    // stage tile at k0 into buffer bufid
#define STAGE_PRE(k0, bufid)                                                      \
    {                                                                             \
        float* Abh = smem + (bufid) * BUFP;                                       \
        float* Abl = Abh + ASZ;                                                   \
        float* Bbh = Abh + 2 * ASZ;                                               \
        float* Bbl = Bbh + BSZ;                                                   \
        _Pragma("unroll")                                                         \
        for (int p = 0; p < 4; p++) {                                             \
            int r = ar + p * 32;                                                  \
            cp16(Abh + r * 36 + ac0, Ah + (size_t)(tileM + r) * K + (k0) + ac0);  \
            cp16(Abl + r * 36 + ac0, Al + (size_t)(tileM + r) * K + (k0) + ac0);  \
        }                                                                         \
        _Pragma("unroll")                                                         \
        for (int p = 0; p < 4; p++) {                                             \
            int kk = bk + p * 8;                                                  \
            cp16(Bbh + kk * 136 + bn0, Bh + (size_t)((k0) + kk) * N + tileN + bn0);\
            cp16(Bbl + kk * 136 + bn0, Bl + (size_t)((k0) + kk) * N + tileN + bn0);\
        }                                                                         \
        asm volatile("cp.async.commit_group;" ::: "memory");                      \
    }

    STAGE_PRE(0, 0);

    for (int i = 0; i < niter; i++) {
        if (i + 1 < niter) {
            STAGE_PRE((i + 1) << 5, (i + 1) & 1);
            asm volatile("cp.async.wait_group 1;" ::: "memory");
        } else {
            asm volatile("cp.async.wait_group 0;" ::: "memory");
        }
        __syncthreads();

        const float* Abh = smem + (i & 1) * BUFP;
        const float* Abl = Abh + ASZ;
        const float* Bbh = Abh + 2 * ASZ;
        const float* Bbl = Bbh + BSZ;
#pragma unroll
        for (int kt = 0; kt < 4; kt++) {
            unsigned afh[4][4], afl[4][4], bfh[4][2], bfl[4][2];
#pragma unroll
            for (int mt = 0; mt < 4; mt++) {
                const int ro = (wm * 64 + mt * 16 + g) * 36 + kt * 8 + tg;
                const float* ap = Abh + ro;
                afh[mt][0] = __float_as_uint(ap[0]);
                afh[mt][1] = __float_as_uint(ap[8 * 36]);
                afh[mt][2] = __float_as_uint(ap[4]);
                afh[mt][3] = __float_as_uint(ap[8 * 36 + 4]);
                const float* aq = Abl + ro;
                afl[mt][0] = __float_as_uint(aq[0]);
                afl[mt][1] = __float_as_uint(aq[8 * 36]);
                afl[mt][2] = __float_as_uint(aq[4]);
                afl[mt][3] = __float_as_uint(aq[8 * 36 + 4]);
            }
#pragma unroll
            for (int nt = 0; nt < 4; nt++) {
                const int bo = (kt * 8 + tg) * 136 + wn * 32 + nt * 8 + g;
                const float* bp = Bbh + bo;
                bfh[nt][0] = __float_as_uint(bp[0]);
                bfh[nt][1] = __float_as_uint(bp[4 * 136]);
                const float* bq = Bbl + bo;
                bfl[nt][0] = __float_as_uint(bq[0]);
                bfl[nt][1] = __float_as_uint(bq[4 * 136]);
            }
#pragma unroll
            for (int mt = 0; mt < 4; mt++)
#pragma unroll
                for (int nt = 0; nt < 4; nt++) {
                    mma_tf32(acc[mt][nt], afh[mt], bfl[nt]);   // hi*lo
                    mma_tf32(acc[mt][nt], afl[mt], bfh[nt]);   // lo*hi
                    mma_tf32(acc[mt][nt], afh[mt], bfh[nt]);   // hi*hi
                }
        }
        __syncthreads();
    }

#pragma unroll
    for (int mt = 0; mt < 4; mt++) {
#pragma unroll
        for (int nt = 0; nt < 4; nt++) {
            const int row = tileM + wm * 64 + mt * 16 + g;
            const int col = tileN + wn * 32 + nt * 8 + tg * 2;
            float2 v0 = make_float2(acc[mt][nt][0], acc[mt][nt][1]);
            float2 v1 = make_float2(acc[mt][nt][2], acc[mt][nt][3]);
            size_t i0 = (size_t)row * N + col;
            size_t i1 = (size_t)(row + 8) * N + col;
            if (EPI == 1) {
                float2 a0 = *(const float2*)(Add + i0);
                float2 a1 = *(const float2*)(Add + i1);
                v0.x += a0.x; v0.y += a0.y;
                v1.x += a1.x; v1.y += a1.y;
                *(float2*)(C + i0) = v0;
                *(float2*)(C + i1) = v1;
            } else if (EPI == 2) {
                v0.x = fmaxf(v0.x, 0.f); v0.x *= v0.x;
                v0.y = fmaxf(v0.y, 0.f); v0.y *= v0.y;
                v1.x = fmaxf(v1.x, 0.f); v1.x *= v1.x;
                v1.y = fmaxf(v1.y, 0.f); v1.y *= v1.y;
                float h0, l0, h1, l1, h2, l2, h3, l3;
                split_f(v0.x, h0, l0); split_f(v0.y, h1, l1);
                split_f(v1.x, h2, l2); split_f(v1.y, h3, l3);
                *(float2*)(Ch + i0) = make_float2(h0, h1);
                *(float2*)(Cl + i0) = make_float2(l0, l1);
                *(float2*)(Ch + i1) = make_float2(h2, h3);
                *(float2*)(Cl + i1) = make_float2(l2, l3);
            } else {
                *(float2*)(C + i0) = v0;
                *(float2*)(C + i1) = v1;
            }
        }
    }
}

__global__ void __launch_bounds__(256) gemm_qkv_p() {
    const int z = blockIdx.z;
    const float* Bh = (z == 0) ? g_Wq_hi : (z == 1) ? g_Wk_hi : g_Wv_hi;
    const float* Bl = (z == 0) ? g_Wq_lo : (z == 1) ? g_Wk_lo : g_Wv_lo;
    float* Cp = (z == 0) ? g_q : (z == 1) ? g_k : g_v;
    mma_gemm_pre<0>(g_h_hi, g_h_lo, Bh, Bl, Cp, nullptr, nullptr, nullptr, D_, D_);
}
__global__ void __launch_bounds__(256) gemm_o_p() {
    mma_gemm_pre<1>(g_o_hi, g_o_lo, g_Wo_hi, g_Wo_lo, g_x1, g_xr, nullptr, nullptr, D_, D_);
}
__global__ void __launch_bounds__(256) gemm_fc_p() {
    mma_gemm_pre<2>(g_m_hi, g_m_lo, g_Wfc_hi, g_Wfc_lo, nullptr, nullptr,
                    g_act_hi, g_act_lo, FD_, D_);
}
__global__ void __launch_bounds__(256) gemm_proj_p(float* __restrict__ out) {
    mma_gemm_pre<1>(g_act_hi, g_act_lo, g_Wpr_hi, g_Wpr_lo, out, g_x1, nullptr, nullptr, D_, FD_);
}

// ---------------- gates: tiled, 16 rows x 48 cols per block (R10 proven) ----------------
__global__ void __launch_bounds__(768) k_gate2(const float* __restrict__ Wg) {
    __shared__ float sh[16 * 128];
    __shared__ float sw[128 * 48];
    const int t = threadIdx.x;
    const int r = t / 48, c = t % 48;
    const int row0 = blockIdx.x * 16;
    float acc = 0.f;
    for (int k0 = 0; k0 < D_; k0 += 128) {
        for (int i = t; i < 16 * 128; i += 768)
            sh[i] = g_h[(size_t)(row0 + (i >> 7)) * D_ + k0 + (i & 127)];
        for (int i = t; i < 128 * 48; i += 768)
            sw[i] = Wg[(size_t)(k0 + i / 48) * 48 + (i % 48)];
        __syncthreads();
        const float* hr = &sh[r * 128];
#pragma unroll 8
        for (int kk = 0; kk < 128; kk++) acc += hr[kk] * sw[kk * 48 + c];
        __syncthreads();
    }
    g_gate[(size_t)(row0 + r) * 48 + c] = 1.f / (1.f + expf(-acc));
}

// ---------------- block compression (R10 proven): one block per (b,n,h) ----------------
__global__ void k_compress(const float* __restrict__ pos_k, const float* __restrict__ pos_v,
                           const float* __restrict__ Wck, const float* __restrict__ Wcv) {
    const int idx = blockIdx.x;   // B*NB*H = 8192
    const int h = idx & (H_ - 1);
    const int n = (idx >> 4) & (NB_ - 1);
    const int b = idx >> 12;
    const int t = threadIdx.x;    // 64
    __shared__ float kb[256], vb[256];
    for (int r = t; r < 256; r += 64) {
        const int sp = r >> 6, d = r & 63;
        const int s = n * 4 + sp;
        const size_t src = ((size_t)(b * S_ + s) * H_ + h) * DH_ + d;
        kb[r] = g_k[src] + pos_k[(h * 4 + sp) * DH_ + d];
        vb[r] = g_v[src] + pos_v[(h * 4 + sp) * DH_ + d];
    }
    __syncthreads();
    float ak = 0.f, av = 0.f;
    for (int r = 0; r < 256; r++) {
        ak += kb[r] * Wck[r * DH_ + t];
        av += vb[r] * Wcv[r * DH_ + t];
    }
    const size_t dst = ((size_t)(b * NC_ + (n + 1)) * H_ + h) * DH_ + t;
    g_kc[dst] = ak;
    g_vc[dst] = av;
}

__global__ void k_memfill(const float* __restrict__ mem_k, const float* __restrict__ mem_v) {
    const int i = blockIdx.x * blockDim.x + threadIdx.x;  // B*H*DH = 2048
    if (i >= B_ * H_ * DH_) return;
    const int d = i & 63, h = (i >> 6) & (H_ - 1), b = i >> 10;
    const size_t dst = ((size_t)(b * NC_ + 0) * H_ + h) * DH_ + d;
    g_kc[dst] = mem_k[h * DH_ + d];
    g_vc[dst] = mem_v[h * DH_ + d];
}

// ---------------- trig table + RoPE ----------------
__global__ void k_trig() {
    const int i = blockIdx.x * blockDim.x + threadIdx.x;  // S*32
    if (i >= S_ * 32) return;
    const int p = i & 31;
    const int s = i >> 5;
    const float inv = exp2f(-(float)p * (13.287712379549449f / 32.f));
    const float tt = (float)s * inv;
    g_ctab[i] = cosf(tt);
    g_stab[i] = sinf(tt);
}

__global__ void k_rope() {
    const int i = blockIdx.x * blockDim.x + threadIdx.x;  // B*S*H*32
    if (i >= B_ * S_ * H_ * 32) return;
    const int p = i & 31;
    const int h = (i >> 5) & (H_ - 1);
    const int s = (i >> 9) & (S_ - 1);
    const int b = i >> 19;
    const float c  = g_ctab[s * 32 + p];
    const float sn = g_stab[s * 32 + p];
    const size_t base = ((size_t)(b * S_ + s) * H_ + h) * DH_;
    float q1 = g_q[base + p], q2 = g_q[base + 32 + p];
    g_qr[base + p]      = q1 * c - q2 * sn;
    g_qr[base + 32 + p] = q1 * sn + q2 * c;
    float k1 = g_k[base + p], k2 = g_k[base + 32 + p];
    g_kr[base + p]      = k1 * c - k2 * sn;
    g_kr[base + 32 + p] = k1 * sn + k2 * c;
}

// ---------------- attention v3 (R10 proven) + split-epilogue for o ----------------
#define KTP 65     // tile row pitch (floats)

__global__ void __launch_bounds__(256) k_attn3() {
    const int blk = blockIdx.x;            // B*H*(S/8) = 4096
    const int s0 = (blk & 127) << 3;
    const int h = (blk >> 7) & (H_ - 1);
    const int b = blk >> 11;
    const int w = threadIdx.x >> 5;
    const int l = threadIdx.x & 31;
    const int s = s0 + w;
    const int tid = threadIdx.x;

    __shared__ float qs[8][64];
    __shared__ float qrs[8][64];
    __shared__ float sc[8][260];
    __shared__ float buf[5200];

    const size_t qbase = ((size_t)(b * S_ + s) * H_ + h) * DH_;
    qs [w][l]      = g_q [qbase + l];
    qs [w][l + 32] = g_q [qbase + 32 + l];
    qrs[w][l]      = g_qr[qbase + l];
    qrs[w][l + 32] = g_qr[qbase + 32 + l];
    __syncwarp();

    const int nvisB = (s >= 3) ? (((s - 3) >> 2) + 1) : 0;
    const int nk = nvisB + 1;
    const int nkb = (((s0 + 7) >= 3) ? (((s0 + 4) >> 2) + 1) : 0) + 1;

    const float* kcbase = g_kc + ((size_t)b * NC_ * H_ + h) * DH_;
    const float* vcbase = g_vc + ((size_t)b * NC_ * H_ + h) * DH_;
    const float* qsw  = qs[w];
    const float* qrsw = qrs[w];

    // ===== Phase A: compressed scores =====
    float mymax = -1e30f;
    for (int n0 = 0; n0 < nkb; n0 += 64) {
        __syncthreads();
#pragma unroll
        for (int i = 0; i < 16; i++) {
            const int e = tid + 256 * i;
            const int r = e >> 6, c = e & 63;
            int n = n0 + r; if (n > NC_ - 1) n = NC_ - 1;
            buf[r * KTP + c] = kcbase[(size_t)n * (H_ * DH_) + c];
        }
        __syncthreads();
#pragma unroll
        for (int sub = 0; sub < 2; sub++) {
            const int n = n0 + sub * 32 + l;
            if (n < nk) {
                const float* kr_ = &buf[(sub * 32 + l) * KTP];
                float a = 0.f;
#pragma unroll
                for (int d = 0; d < 64; d++) a += qsw[d] * kr_[d];
                a *= 0.125f;
                sc[w][n] = a;
                mymax = fmaxf(mymax, a);
            }
        }
    }
#pragma unroll
    for (int o = 16; o; o >>= 1) mymax = fmaxf(mymax, __shfl_xor_sync(FULLMASK, mymax, o));

    float mysum = 0.f;
    for (int n = l; n < nk; n += 32) {
        float e = expf(sc[w][n] - mymax);
        sc[w][n] = e;
        mysum += e;
    }
#pragma unroll
    for (int o = 16; o; o >>= 1) mysum += __shfl_xor_sync(FULLMASK, mysum, o);
    const float rcs = 1.f / mysum;

    // ===== top-4 blocks =====
    float tv[4] = {-1.f, -1.f, -1.f, -1.f};
    int   ti[4] = {0, 0, 0, 0};
    for (int n = l; n < nk; n += 32) {
        if (n >= 1) {
            float vI = sc[w][n];
            if (vI > tv[3]) {
                int p2 = 3;
                while (p2 > 0 && vI > tv[p2 - 1]) {
                    tv[p2] = tv[p2 - 1]; ti[p2] = ti[p2 - 1]; p2--;
                }
                tv[p2] = vI; ti[p2] = n - 1;
            }
        }
    }
#pragma unroll
    for (int off = 16; off; off >>= 1) {
        float ov[4]; int oi[4];
#pragma unroll
        for (int m = 0; m < 4; m++) {
            ov[m] = __shfl_xor_sync(FULLMASK, tv[m], off);
            oi[m] = __shfl_xor_sync(FULLMASK, ti[m], off);
        }
#pragma unroll
        for (int m = 0; m < 4; m++) {
            float v2 = ov[m]; int i2 = oi[m];
            if ((v2 > tv[3]) || (v2 == tv[3] && i2 < ti[3])) {
                int p2 = 3;
                while (p2 > 0 && ((v2 > tv[p2 - 1]) || (v2 == tv[p2 - 1] && i2 < ti[p2 - 1]))) {
                    tv[p2] = tv[p2 - 1]; ti[p2] = ti[p2 - 1]; p2--;
                }
                tv[p2] = v2; ti[p2] = i2;
            }
        }
    }

    // ===== Phase B: compressed PV =====
    float oc0 = 0.f, oc1 = 0.f;
    for (int n0 = 0; n0 < nkb; n0 += 64) {
        __syncthreads();
#pragma unroll
        for (int i = 0; i < 16; i++) {
            const int e = tid + 256 * i;
            const int r = e >> 6, c = e & 63;
            int n = n0 + r; if (n > NC_ - 1) n = NC_ - 1;
            buf[r * KTP + c] = vcbase[(size_t)n * (H_ * DH_) + c];
        }
        __syncthreads();
        const int jmax = (nk - n0 < 64) ? (nk - n0) : 64;
        for (int j = 0; j < jmax; j++) {
            const float pn = sc[w][n0 + j];
            oc0 += pn * buf[j * KTP + l];
            oc1 += pn * buf[j * KTP + l + 32];
        }
    }
    oc0 *= rcs; oc1 *= rcs;

    // ===== Phase C: fine (20 gathered keys) =====
    float fe = 0.f;
    int fkp = 0;
    {
        float fs = -1e30f;
        if (l < 20) {
            const int m = l >> 2, sp = l & 3;
            const int blk2 = (m == 4) ? (s >> 2) : ti[m];
            fkp = blk2 * 4 + sp;
            const bool vis = ((m == 4) || (tv[m] > 0.f)) && (fkp <= s);
            if (vis) {
                const float* kp = g_kr + ((size_t)(b * S_ + fkp) * H_ + h) * DH_;
                fs = 0.f;
#pragma unroll
                for (int d = 0; d < 64; d += 4) {
                    float4 x = *(const float4*)(qrsw + d);
                    float4 y = *(const float4*)(kp + d);
                    fs += x.x * y.x + x.y * y.y + x.z * y.z + x.w * y.w;
                }
                fs *= 0.125f;
            }
        }
        float fmx = fs;
#pragma unroll
        for (int o = 16; o; o >>= 1) fmx = fmaxf(fmx, __shfl_xor_sync(FULLMASK, fmx, o));
        fe = (fs > -1e29f) ? expf(fs - fmx) : 0.f;
    }
    float fsum = fe;
#pragma unroll
    for (int o = 16; o; o >>= 1) fsum += __shfl_xor_sync(FULLMASK, fsum, o);
    const float rcf = 1.f / fsum;

    float of0 = 0.f, of1 = 0.f;
    for (int j = 0; j < 20; j++) {
        float pj = __shfl_sync(FULLMASK, fe, j);
        int kj   = __shfl_sync(FULLMASK, fkp, j);
        const float* p = g_v + ((size_t)(b * S_ + kj) * H_ + h) * DH_;
        of0 += pj * p[l];
        of1 += pj * p[l + 32];
    }
    of0 *= rcf; of1 *= rcf;

    // ===== Phase D: sliding window =====
    __syncthreads();
    {
        const int base = s0 - 31;
#pragma unroll
        for (int i = 0; i < 10; i++) {
            const int e = tid + 256 * i;
            const int r = e >> 6, c = e & 63;
            int rs = base + r; if (rs < 0) rs = 0;
            const size_t src = ((size_t)(b * S_ + rs) * H_ + h) * DH_ + c;
            buf[r * KTP + c]        = g_kr[src];
            buf[2600 + r * KTP + c] = g_v [src];
        }
    }
    __syncthreads();

    float se = 0.f;
    {
        const int pos = s - l;
        float ssv = -1e30f;
        if (pos >= 0) {
            const float* kr_ = &buf[(w + 31 - l) * KTP];
            ssv = 0.f;
#pragma unroll
            for (int d = 0; d < 64; d++) ssv += qrsw[d] * kr_[d];
            ssv *= 0.125f;
        }
        float smx = ssv;
#pragma unroll
        for (int o = 16; o; o >>= 1) smx = fmaxf(smx, __shfl_xor_sync(FULLMASK, smx, o));
        se = (ssv > -1e29f) ? expf(ssv - smx) : 0.f;
    }
    float ssum = se;
#pragma unroll
    for (int o = 16; o; o >>= 1) ssum += __shfl_xor_sync(FULLMASK, ssum, o);
    const float rcw = 1.f / ssum;

    float os0 = 0.f, os1 = 0.f;
    {
        const int wmax = s < 31 ? s : 31;
        for (int w2 = 0; w2 <= wmax; w2++) {
            float pj = __shfl_sync(FULLMASK, se, w2);
            const float* vr = &buf[2600 + (w + 31 - w2) * KTP];
            os0 += pj * vr[l];
            os1 += pj * vr[l + 32];
        }
    }
    os0 *= rcw; os1 *= rcw;

    // ===== gate + split-store of o (feeds only gemm_o) =====
    const float* gg = g_gate + (size_t)(b * S_ + s) * 48 + h * 3;
    const float g0 = gg[0], g1 = gg[1], g2 = gg[2];
    const float o0 = g0 * oc0 + g1 * of0 + g2 * os0;
    const float o1 = g0 * oc1 + g1 * of1 + g2 * os1;
    const size_t oi = (size_t)(b * S_ + s) * D_ + h * DH_ + l;
    float hi, lo;
    split_f(o0, hi, lo); g_o_hi[oi] = hi;      g_o_lo[oi] = lo;
    split_f(o1, hi, lo); g_o_hi[oi + 32] = hi; g_o_lo[oi + 32] = lo;
}

// ---------------- launch ----------------
extern "C" void kernel_launch(void* const* d_in, const int* in_sizes, int n_in,
                              void* d_out, int out_size) {
    (void)in_sizes; (void)n_in; (void)out_size;
    const float* x     = (const float*)d_in[0];
    const float* x0    = (const float*)d_in[2];
    const float* lam   = (const float*)d_in[3];
    const float* Wq    = (const float*)d_in[4];
    const float* Wk    = (const float*)d_in[5];
    const float* Wv    = (const float*)d_in[6];
    const float* pos_k = (const float*)d_in[7];
    const float* pos_v = (const float*)d_in[8];
    const float* Wck   = (const float*)d_in[9];
    const float* Wcv   = (const float*)d_in[10];
    const float* mem_k = (const float*)d_in[11];
    const float* mem_v = (const float*)d_in[12];
    const float* Wg    = (const float*)d_in[13];
    const float* Wo    = (const float*)d_in[14];
    const float* Wfc   = (const float*)d_in[15];
    const float* Wproj = (const float*)d_in[16];
    float* out = (float*)d_out;

    cudaFuncSetAttribute(gemm_qkv_p,  cudaFuncAttributeMaxDynamicSharedMemorySize, SMEM_PRE_BYTES);
    cudaFuncSetAttribute(gemm_o_p,    cudaFuncAttributeMaxDynamicSharedMemorySize, SMEM_PRE_BYTES);
    cudaFuncSetAttribute(gemm_fc_p,   cudaFuncAttributeMaxDynamicSharedMemorySize, SMEM_PRE_BYTES);
    cudaFuncSetAttribute(gemm_proj_p, cudaFuncAttributeMaxDynamicSharedMemorySize, SMEM_PRE_BYTES);

    // weight splits (independent of activations)
    {
        float *h_, *l_;
        cudaGetSymbolAddress((void**)&h_, g_Wq_hi);  cudaGetSymbolAddress((void**)&l_, g_Wq_lo);
        k_wsplit<<<(D_*D_)/256, 256>>>(Wq, h_, l_, D_*D_);
        cudaGetSymbolAddress((void**)&h_, g_Wk_hi);  cudaGetSymbolAddress((void**)&l_, g_Wk_lo);
        k_wsplit<<<(D_*D_)/256, 256>>>(Wk, h_, l_, D_*D_);
        cudaGetSymbolAddress((void**)&h_, g_Wv_hi);  cudaGetSymbolAddress((void**)&l_, g_Wv_lo);
        k_wsplit<<<(D_*D_)/256, 256>>>(Wv, h_, l_, D_*D_);
        cudaGetSymbolAddress((void**)&h_, g_Wo_hi);  cudaGetSymbolAddress((void**)&l_, g_Wo_lo);
        k_wsplit<<<(D_*D_)/256, 256>>>(Wo, h_, l_, D_*D_);
        cudaGetSymbolAddress((void**)&h_, g_Wfc_hi); cudaGetSymbolAddress((void**)&l_, g_Wfc_lo);
        k_wsplit<<<(D_*FD_)/256, 256>>>(Wfc, h_, l_, D_*FD_);
        cudaGetSymbolAddress((void**)&h_, g_Wpr_hi); cudaGetSymbolAddress((void**)&l_, g_Wpr_lo);
        k_wsplit<<<(FD_*D_)/256, 256>>>(Wproj, h_, l_, FD_*D_);
    }

    k_trig<<<(S_ * 32) / 256, 256>>>();
    k_rms1<<<ROWS_, 256>>>(x, x0, lam);

    dim3 gqkv(D_ / 128, ROWS_ / 128, 3);   // (8,16,3)
    gemm_qkv_p<<<gqkv, 256, SMEM_PRE_BYTES>>>();
    k_gate2<<<ROWS_ / 16, 768>>>(Wg);

    k_compress<<<B_ * NB_ * H_, 64>>>(pos_k, pos_v, Wck, Wcv);
    k_memfill<<<(B_ * H_ * DH_ + 255) / 256, 256>>>(mem_k, mem_v);
    k_rope<<<(B_ * S_ * H_ * 32) / 256, 256>>>();

    k_attn3<<<B_ * H_ * (S_ / 8), 256>>>();

    dim3 g1(D_ / 128, ROWS_ / 128);        // (8,16)
    gemm_o_p<<<g1, 256, SMEM_PRE_BYTES>>>();       // x1 = xr + o@Wo
    k_rms2<<<ROWS_, 256>>>();                      // m = rmsnorm(x1) (split)

    dim3 g2(FD_ / 128, ROWS_ / 128);       // (32,16)
    gemm_fc_p<<<g2, 256, SMEM_PRE_BYTES>>>();      // act = relu(m@Wfc)^2 (split)
    gemm_proj_p<<<g1, 256, SMEM_PRE_BYTES>>>(out); // out = x1 + act@Wproj
}